// round 6
// baseline (speedup 1.0000x reference)
#include <cuda_runtime.h>
#include <cuda_fp16.h>
#include <math.h>
#include <stdint.h>

#define BDIM  16384
#define H_DIM 1024
#define A_DIM 20
#define K_DIM 4096

#define BM 128
#define BN 256
#define BK 64
#define NSTAGE (K_DIM / BK)      // 64
#define STAGEB 98304             // 96 KB per stage buffer
#define NTILES (H_DIM / BN)      // 4
#define W_SCALE 2048.0f
#define INV_W_SCALE (1.0f / 2048.0f)
#define HS_STRIDE 260            // h-tile smem row stride (floats)

// Static scratch (no allocations allowed)
__device__ __align__(1024) __half g_Ahi[(size_t)BDIM * K_DIM];     // 128 MB
__device__ __align__(1024) __half g_Alo[(size_t)BDIM * K_DIM];     // 128 MB
__device__ __align__(1024) __half g_Bhi[(size_t)H_DIM * K_DIM];    // 8 MB (2048*W1^T hi)
__device__ __align__(1024) __half g_Blo[(size_t)H_DIM * K_DIM];    // 8 MB
__device__ __align__(1024) float  g_part[(size_t)NTILES * BDIM * A_DIM];  // 5.2 MB

// ---------------------------------------------------------------- helpers --
__device__ __forceinline__ uint32_t smem_u32(const void* p) {
    uint32_t a;
    asm("{ .reg .u64 t; cvta.to.shared.u64 t, %1; cvt.u32.u64 %0, t; }"
        : "=r"(a) : "l"(p));
    return a;
}
__device__ __forceinline__ void cp_async16(uint32_t dst, const void* src) {
    asm volatile("cp.async.cg.shared.global [%0], [%1], 16;" :: "r"(dst), "l"(src));
}
#define SW128(o) ((o) ^ (((o) >> 3) & 0x70))

#define LDSM4(r, addr) \
    asm volatile("ldmatrix.sync.aligned.m8n8.x4.shared.b16 {%0,%1,%2,%3}, [%4];" \
        : "=r"((r)[0]), "=r"((r)[1]), "=r"((r)[2]), "=r"((r)[3]) : "r"(addr))

__device__ __forceinline__ void mma_f16(float* c, const uint32_t* a, const uint32_t* b) {
    asm volatile(
        "mma.sync.aligned.m16n8k16.row.col.f32.f16.f16.f32 "
        "{%0,%1,%2,%3},{%4,%5,%6,%7},{%8,%9},{%0,%1,%2,%3};"
        : "+f"(c[0]), "+f"(c[1]), "+f"(c[2]), "+f"(c[3])
        : "r"(a[0]), "r"(a[1]), "r"(a[2]), "r"(a[3]), "r"(b[0]), "r"(b[1]));
}

// ------------------------------------------------------------- pre-passes --
__global__ __launch_bounds__(256) void splitA_kernel(
    const float* __restrict__ x0, const float* __restrict__ x1,
    const float* __restrict__ x2, const float* __restrict__ x3)
{
    const size_t i = (size_t)blockIdx.x * blockDim.x + threadIdx.x;  // float4 idx
    if (i >= (size_t)BDIM * K_DIM / 4) return;
    const size_t m = i >> 10;
    const int kq = (int)(i & 1023);
    const int part = kq >> 8;
    const int kin = (kq & 255) * 4;
    const float* xs = part == 0 ? x0 : part == 1 ? x1 : part == 2 ? x2 : x3;
    float4 a = *(const float4*)(xs + m * H_DIM + kin);

    __half h0 = __float2half_rn(a.x), h1 = __float2half_rn(a.y);
    __half h2 = __float2half_rn(a.z), h3 = __float2half_rn(a.w);
    __half l0 = __float2half_rn(a.x - __half2float(h0));
    __half l1 = __float2half_rn(a.y - __half2float(h1));
    __half l2 = __float2half_rn(a.z - __half2float(h2));
    __half l3 = __float2half_rn(a.w - __half2float(h3));

    __half2* ph = (__half2*)(g_Ahi + i * 4);
    __half2* pl = (__half2*)(g_Alo + i * 4);
    ph[0] = __halves2half2(h0, h1); ph[1] = __halves2half2(h2, h3);
    pl[0] = __halves2half2(l0, l1); pl[1] = __halves2half2(l2, l3);
}

__global__ void splitB_kernel(const float* __restrict__ W1)
{
    __shared__ float tile[32][33];
    const int k0 = blockIdx.y * 32;
    const int n0 = blockIdx.x * 32;
    const int tx = threadIdx.x, ty = threadIdx.y;
#pragma unroll
    for (int j = 0; j < 32; j += 8)
        tile[ty + j][tx] = W1[(size_t)(k0 + ty + j) * H_DIM + n0 + tx];
    __syncthreads();
#pragma unroll
    for (int j = 0; j < 32; j += 8) {
        const int n = n0 + ty + j, k = k0 + tx;
        const float v = tile[tx][ty + j] * W_SCALE;
        const __half h = __float2half_rn(v);
        g_Bhi[(size_t)n * K_DIM + k] = h;
        g_Blo[(size_t)n * K_DIM + k] = __float2half_rn(v - __half2float(h));
    }
}

// ------------------------- stage 1: fp16x3 mma GEMM + fused logit partials --
__global__ __launch_bounds__(512, 1) void gemm1_fp16_kernel(
    const float* __restrict__ b1, const float* __restrict__ W2)
{
    extern __shared__ char smem[];
    const uint32_t sb = smem_u32(smem);
    const int tid  = threadIdx.x;
    const int wid  = tid >> 5;
    const int lane = tid & 31;
    const int wm = wid & 3;     // 4 m-tiles of 32
    const int wn = wid >> 2;    // 4 n-tiles of 64
    const int bm = blockIdx.y * BM;
    const int bn = blockIdx.x * BN;

    auto load_stage = [&](int t) {
        const int st = t & 1;
        const int k0 = t * BK;
        const uint32_t base = sb + st * STAGEB;
#pragma unroll
        for (int c = 0; c < 4; c++) {                 // A: 2048 chunks
            const int idx = c * 512 + tid;
            const int plane = idx >> 10, rem = idx & 1023;
            const int r = rem >> 3, seg = rem & 7;
            const __half* gp = plane ? g_Alo : g_Ahi;
            cp_async16(base + plane * 16384 + SW128((uint32_t)(r * 128 + seg * 16)),
                       gp + (size_t)(bm + r) * K_DIM + k0 + seg * 8);
        }
#pragma unroll
        for (int c = 0; c < 8; c++) {                 // B: 4096 chunks
            const int idx = c * 512 + tid;
            const int plane = idx >> 11, rem = idx & 2047;
            const int r = rem >> 3, seg = rem & 7;
            const __half* gp = plane ? g_Blo : g_Bhi;
            cp_async16(base + 32768 + plane * 32768 + SW128((uint32_t)(r * 128 + seg * 16)),
                       gp + (size_t)(bn + r) * K_DIM + k0 + seg * 8);
        }
        asm volatile("cp.async.commit_group;" ::: "memory");
    };

    float acc[2][8][4];
#pragma unroll
    for (int i = 0; i < 2; i++)
#pragma unroll
        for (int j = 0; j < 8; j++)
#pragma unroll
            for (int q = 0; q < 4; q++) acc[i][j][q] = 0.f;

    load_stage(0);
    load_stage(1);
    asm volatile("cp.async.wait_group 1;" ::: "memory");
    __syncthreads();

    const int rA = wm * 32 + (lane & 15);
    const int rB0 = wn * 64 + (lane & 15);
    const int sseg = lane >> 4;

    for (int t = 0; t < NSTAGE; ++t) {
        const uint32_t base = sb + (t & 1) * STAGEB;
#pragma unroll
        for (int ks = 0; ks < 4; ks++) {
            uint32_t ah[2][4], al[2][4];
#pragma unroll
            for (int i = 0; i < 2; i++) {
                const int r = rA + i * 16;
                const uint32_t addr = base + (uint32_t)(r * 128)
                                    + ((uint32_t)((ks * 2 + sseg) ^ (r & 7)) << 4);
                LDSM4(ah[i], addr);
                LDSM4(al[i], addr + 16384);
            }
            uint32_t bb[4][4];
#pragma unroll
            for (int p = 0; p < 4; p++) {
                const int r = rB0 + p * 16;
                const uint32_t addr = base + 32768 + (uint32_t)(r * 128)
                                    + ((uint32_t)((ks * 2 + sseg) ^ (r & 7)) << 4);
                LDSM4(bb[p], addr);
            }
#pragma unroll
            for (int j = 0; j < 8; j++) {
                uint32_t bf[2] = { bb[j >> 1][j & 1], bb[j >> 1][(j & 1) + 2] };
                mma_f16(acc[0][j], ah[0], bf);
                mma_f16(acc[1][j], ah[1], bf);
                mma_f16(acc[0][j], al[0], bf);
                mma_f16(acc[1][j], al[1], bf);
            }
#pragma unroll
            for (int p = 0; p < 4; p++) {
                const int r = rB0 + p * 16;
                const uint32_t addr = base + 65536 + (uint32_t)(r * 128)
                                    + ((uint32_t)((ks * 2 + sseg) ^ (r & 7)) << 4);
                LDSM4(bb[p], addr);
            }
#pragma unroll
            for (int j = 0; j < 8; j++) {
                uint32_t bf[2] = { bb[j >> 1][j & 1], bb[j >> 1][(j & 1) + 2] };
                mma_f16(acc[0][j], ah[0], bf);
                mma_f16(acc[1][j], ah[1], bf);
            }
        }
        __syncthreads();
        if (t + 2 < NSTAGE) {
            load_stage(t + 2);
            asm volatile("cp.async.wait_group 1;" ::: "memory");
        } else {
            asm volatile("cp.async.wait_group 0;" ::: "memory");
        }
        __syncthreads();
    }

    // ---- fused epilogue: tanh tile -> smem, mini-GEMM vs W2 slice ----
    float* hs  = (float*)smem;                         // [128][HS_STRIDE]
    float* w2s = (float*)(smem + 128 * HS_STRIDE * 4); // [20][256]

    const int g  = lane >> 2;
    const int tq = lane & 3;
#pragma unroll
    for (int j = 0; j < 8; j++) {
        const int colL = wn * 64 + j * 8 + tq * 2;
        const int col  = bn + colL;
        const float bb0 = __ldg(&b1[col]);
        const float bb1 = __ldg(&b1[col + 1]);
#pragma unroll
        for (int i = 0; i < 2; i++) {
            const int rowL = wm * 32 + i * 16 + g;
            float2 v0, v1;
            v0.x = tanhf(fmaf(acc[i][j][0], INV_W_SCALE, bb0));
            v0.y = tanhf(fmaf(acc[i][j][1], INV_W_SCALE, bb1));
            v1.x = tanhf(fmaf(acc[i][j][2], INV_W_SCALE, bb0));
            v1.y = tanhf(fmaf(acc[i][j][3], INV_W_SCALE, bb1));
            *(float2*)(hs + (size_t)rowL * HS_STRIDE + colL)       = v0;
            *(float2*)(hs + (size_t)(rowL + 8) * HS_STRIDE + colL) = v1;
        }
    }
    // W2 slice transposed: w2s[a][c] = W2[(bn+c)*20 + a]
    for (int idx = tid; idx < A_DIM * BN; idx += 512) {
        const int a = idx >> 8;
        const int c = idx & 255;
        w2s[a * BN + c] = __ldg(&W2[(size_t)(bn + c) * A_DIM + a]);
    }
    __syncthreads();

    // mini-GEMM: warp w -> rows w*8..w*8+7; partial logits over 256 cols
    const int r0 = wid * 8;
    for (int rr = 0; rr < 8; rr++) {
        const int r = r0 + rr;
        float a20[A_DIM];
#pragma unroll
        for (int a = 0; a < A_DIM; a++) a20[a] = 0.f;
#pragma unroll
        for (int j = 0; j < 8; j++) {
            const int c = lane + 32 * j;
            const float hv = hs[(size_t)r * HS_STRIDE + c];
#pragma unroll
            for (int a = 0; a < A_DIM; a++)
                a20[a] = fmaf(hv, w2s[a * BN + c], a20[a]);
        }
#pragma unroll
        for (int off = 16; off > 0; off >>= 1)
#pragma unroll
            for (int a = 0; a < A_DIM; a++)
                a20[a] += __shfl_xor_sync(0xffffffffu, a20[a], off);

        const size_t pbase = ((size_t)blockIdx.x * BDIM + bm + r) * A_DIM;
#pragma unroll
        for (int a = 0; a < A_DIM; a++)
            if (lane == a) g_part[pbase + a] = a20[a];
    }
}

// ------------------------------------------------------------- finalize ---
__global__ __launch_bounds__(256) void finalize_kernel(
    const float* __restrict__ b2,
    const void* __restrict__ valid_mask,
    const int* __restrict__ real_actions,
    float* __restrict__ out, int B, int write_pred)
{
    __shared__ int s_mode;
    if (threadIdx.x == 0) {
        const unsigned int* m = (const unsigned int*)valid_mask;
        bool f32 = false, bf16 = false, multi = false;
#pragma unroll
        for (int i = 0; i < 64; i++) {
            unsigned int w = m[i];
            if (w == 0x3F800000u) f32 = true;
            else if (w == 0x3F803F80u || w == 0x00003F80u) bf16 = true;
            else if (w > 1u) multi = true;
        }
        s_mode = bf16 ? 3 : f32 ? 2 : multi ? 0 : 1;
    }
    __syncthreads();

    const int row = blockIdx.x * blockDim.x + threadIdx.x;
    if (row >= B) return;

    float logit[A_DIM];
#pragma unroll
    for (int a = 0; a < A_DIM; a++) logit[a] = __ldg(&b2[a]);
#pragma unroll
    for (int p = 0; p < NTILES; p++) {
        const float* pp = g_part + ((size_t)p * BDIM + row) * A_DIM;
#pragma unroll
        for (int q = 0; q < 5; q++) {
            float4 v = *(const float4*)(pp + q * 4);
            logit[q * 4 + 0] += v.x;
            logit[q * 4 + 1] += v.y;
            logit[q * 4 + 2] += v.z;
            logit[q * 4 + 3] += v.w;
        }
    }

    const int mode = s_mode;
    const long base = (long)row * A_DIM;
    float masked[A_DIM];
    float m = -3.0e38f;
#pragma unroll
    for (int a = 0; a < A_DIM; a++) {
        bool valid;
        if (mode == 1)      valid = ((const int*)valid_mask)[base + a] != 0;
        else if (mode == 2) valid = ((const float*)valid_mask)[base + a] != 0.0f;
        else if (mode == 0) valid = ((const unsigned char*)valid_mask)[base + a] != 0;
        else                valid = ((const unsigned short*)valid_mask)[base + a] != 0;
        masked[a] = valid ? logit[a] : -1e9f;
        m = fmaxf(m, masked[a]);
    }
    float s = 0.f;
#pragma unroll
    for (int a = 0; a < A_DIM; a++) s += expf(masked[a] - m);
    const float lse = m + logf(s);

    int pred = 0;
    float best = masked[0];
#pragma unroll
    for (int a = 1; a < A_DIM; a++)
        if (masked[a] > best) { best = masked[a]; pred = a; }

    const int gold = real_actions[row];
    const float loss = masked[gold] - lse;

    if (write_pred) {
        out[row]     = (float)pred;
        out[B + row] = loss;
    } else {
        out[row] = loss;
    }
}

// ---------------------------------------------------------------- launch --
extern "C" void kernel_launch(void* const* d_in, const int* in_sizes, int n_in,
                              void* d_out, int out_size)
{
    const float* buffer_h = (const float*)d_in[0];
    const float* stack_h  = (const float*)d_in[1];
    const float* output_h = (const float*)d_in[2];
    const float* action_h = (const float*)d_in[3];
    const float* W1 = (const float*)d_in[4];
    const float* b1 = (const float*)d_in[5];
    const float* W2 = (const float*)d_in[6];
    const float* b2 = (const float*)d_in[7];
    const void* valid_mask = d_in[8];
    const int* real_actions = (const int*)d_in[9];
    float* out = (float*)d_out;

    const int B = in_sizes[0] / H_DIM;  // 16384

    const size_t totalA4 = (size_t)B * K_DIM / 4;
    splitA_kernel<<<(unsigned)((totalA4 + 255) / 256), 256>>>(buffer_h, stack_h,
                                                              output_h, action_h);
    splitB_kernel<<<dim3(H_DIM / 32, K_DIM / 32), dim3(32, 8)>>>(W1);

    const int smem1 = 2 * STAGEB;  // 192 KB (epilogue reuse fits inside)
    cudaFuncSetAttribute(gemm1_fp16_kernel,
                         cudaFuncAttributeMaxDynamicSharedMemorySize, smem1);
    dim3 grid1(H_DIM / BN, B / BM);   // (4, 128)
    gemm1_fp16_kernel<<<grid1, 512, smem1>>>(b1, W2);

    const int write_pred = (out_size >= 2 * B) ? 1 : 0;
    finalize_kernel<<<(B + 255) / 256, 256>>>(b2, valid_mask, real_actions,
                                              out, B, write_pred);
}

// round 7
// speedup vs baseline: 1.0130x; 1.0130x over previous
#include <cuda_runtime.h>
#include <cuda_fp16.h>
#include <math.h>
#include <stdint.h>

#define BDIM  16384
#define H_DIM 1024
#define A_DIM 20
#define K_DIM 4096

#define BM 128
#define BN 256
#define BK 64
#define NSTAGE (K_DIM / BK)      // 64
#define STAGEB 98304             // 96 KB per stage: Ahi 16K | Alo 16K | Bhi 32K | Blo 32K
#define W_SCALE 2048.0f
#define INV_W_SCALE (1.0f / 2048.0f)

// Static scratch (no allocations allowed)
__device__ __align__(1024) float  g_hidden[(size_t)BDIM * H_DIM];  // 64 MB
__device__ __align__(1024) __half g_Bhi[(size_t)H_DIM * K_DIM];    // 8 MB (2048*W1^T hi)
__device__ __align__(1024) __half g_Blo[(size_t)H_DIM * K_DIM];    // 8 MB

// ---------------------------------------------------------------- helpers --
__device__ __forceinline__ uint32_t smem_u32(const void* p) {
    uint32_t a;
    asm("{ .reg .u64 t; cvta.to.shared.u64 t, %1; cvt.u32.u64 %0, t; }"
        : "=r"(a) : "l"(p));
    return a;
}
__device__ __forceinline__ void cp_async16(uint32_t dst, const void* src) {
    asm volatile("cp.async.cg.shared.global [%0], [%1], 16;" :: "r"(dst), "l"(src));
}
#define SW128(o) ((o) ^ (((o) >> 3) & 0x70))

#define LDSM4(r, addr) \
    asm volatile("ldmatrix.sync.aligned.m8n8.x4.shared.b16 {%0,%1,%2,%3}, [%4];" \
        : "=r"((r)[0]), "=r"((r)[1]), "=r"((r)[2]), "=r"((r)[3]) : "r"(addr))

__device__ __forceinline__ void mma_f16(float* c, const uint32_t* a, const uint32_t* b) {
    asm volatile(
        "mma.sync.aligned.m16n8k16.row.col.f32.f16.f16.f32 "
        "{%0,%1,%2,%3},{%4,%5,%6,%7},{%8,%9},{%0,%1,%2,%3};"
        : "+f"(c[0]), "+f"(c[1]), "+f"(c[2]), "+f"(c[3])
        : "r"(a[0]), "r"(a[1]), "r"(a[2]), "r"(a[3]), "r"(b[0]), "r"(b[1]));
}
__device__ __forceinline__ uint32_t pack_h2(float a, float b) {
    __half2 h = __halves2half2(__float2half_rn(a), __float2half_rn(b));
    return *(uint32_t*)&h;
}

// ------------------------------------------------------------- pre-pass ---
// Transpose W1 [4096,1024] -> [1024,4096], scale by 2048, split fp16 hi/lo
__global__ void splitB_kernel(const float* __restrict__ W1)
{
    __shared__ float tile[32][33];
    const int k0 = blockIdx.y * 32;
    const int n0 = blockIdx.x * 32;
    const int tx = threadIdx.x, ty = threadIdx.y;
#pragma unroll
    for (int j = 0; j < 32; j += 8)
        tile[ty + j][tx] = W1[(size_t)(k0 + ty + j) * H_DIM + n0 + tx];
    __syncthreads();
#pragma unroll
    for (int j = 0; j < 32; j += 8) {
        const int n = n0 + ty + j, k = k0 + tx;
        const float v = tile[tx][ty + j] * W_SCALE;
        const __half h = __float2half_rn(v);
        g_Bhi[(size_t)n * K_DIM + k] = h;
        g_Blo[(size_t)n * K_DIM + k] = __float2half_rn(v - __half2float(h));
    }
}

// -------------------- stage 1: fp16x3 mma GEMM with in-loop A split --------
__global__ __launch_bounds__(512, 1) void gemm1_fp16_kernel(
    const float* __restrict__ x0, const float* __restrict__ x1,
    const float* __restrict__ x2, const float* __restrict__ x3,
    const float* __restrict__ b1)
{
    extern __shared__ char smem[];
    const uint32_t sb = smem_u32(smem);
    const int tid  = threadIdx.x;
    const int wid  = tid >> 5;
    const int lane = tid & 31;
    const int wm = wid & 3;     // 4 m-tiles of 32
    const int wn = wid >> 2;    // 4 n-tiles of 64
    const int bm = blockIdx.y * BM;
    const int bn = blockIdx.x * BN;

    const float* xs[4] = {x0, x1, x2, x3};

    // A loader mapping: thread -> (row, 16-wide k chunk)
    const int ar  = tid >> 2;            // 0..127
    const int akc = (tid & 3) * 16;      // 0,16,32,48

    // prefetch stage-t A f32 into registers (16 floats = 4 float4)
    auto ldgA = [&](int t, float4* p) {
        const int kg0 = t * BK;
        const float* src = xs[kg0 >> 10];
        const float* g = src + (size_t)(bm + ar) * H_DIM + (kg0 & 1023) + akc;
        p[0] = __ldg((const float4*)g);
        p[1] = __ldg((const float4*)(g + 4));
        p[2] = __ldg((const float4*)(g + 8));
        p[3] = __ldg((const float4*)(g + 12));
    };
    // convert regs -> f16 hi/lo, store to swizzled smem planes
    auto stsA = [&](int t, const float4* p) {
        const float* f = (const float*)p;
        uint4 H0, H1, L0, L1;
        uint32_t* H = (uint32_t*)&H0;  // H0,H1 contiguous? no — pack explicitly
        uint32_t hh[8], ll[8];
#pragma unroll
        for (int e = 0; e < 8; e++) {
            const float a = f[2 * e], b = f[2 * e + 1];
            const __half ha = __float2half_rn(a), hb = __float2half_rn(b);
            hh[e] = pack_h2(a, b);
            ll[e] = pack_h2(a - __half2float(ha), b - __half2float(hb));
        }
        H0 = make_uint4(hh[0], hh[1], hh[2], hh[3]);
        H1 = make_uint4(hh[4], hh[5], hh[6], hh[7]);
        L0 = make_uint4(ll[0], ll[1], ll[2], ll[3]);
        L1 = make_uint4(ll[4], ll[5], ll[6], ll[7]);
        char* buf = smem + (t & 1) * STAGEB;
        const uint32_t o0 = SW128((uint32_t)(ar * 128 + akc * 2));
        const uint32_t o1 = SW128((uint32_t)(ar * 128 + akc * 2 + 16));
        *(uint4*)(buf + o0)         = H0;
        *(uint4*)(buf + o1)         = H1;
        *(uint4*)(buf + 16384 + o0) = L0;
        *(uint4*)(buf + 16384 + o1) = L1;
        (void)H;
    };
    // B tiles via cp.async from pre-split planes
    auto load_B = [&](int t) {
        const uint32_t base = sb + (t & 1) * STAGEB;
        const int k0 = t * BK;
#pragma unroll
        for (int c = 0; c < 8; c++) {                 // 4096 16B chunks
            const int idx = c * 512 + tid;
            const int plane = idx >> 11, rem = idx & 2047;
            const int r = rem >> 3, seg = rem & 7;
            const __half* gp = plane ? g_Blo : g_Bhi;
            cp_async16(base + 32768 + plane * 32768 + SW128((uint32_t)(r * 128 + seg * 16)),
                       gp + (size_t)(bn + r) * K_DIM + k0 + seg * 8);
        }
        asm volatile("cp.async.commit_group;" ::: "memory");
    };

    float acc[2][8][4];
#pragma unroll
    for (int i = 0; i < 2; i++)
#pragma unroll
        for (int j = 0; j < 8; j++)
#pragma unroll
            for (int q = 0; q < 4; q++) acc[i][j][q] = 0.f;

    // prologue
    float4 pa[4];
    ldgA(0, pa);
    stsA(0, pa);
    load_B(0);
    ldgA(1, pa);
    stsA(1, pa);
    load_B(1);
    asm volatile("cp.async.wait_group 1;" ::: "memory");
    __syncthreads();

    const int rA = wm * 32 + (lane & 15);
    const int rB0 = wn * 64 + (lane & 15);
    const int sseg = lane >> 4;

    for (int t = 0; t < NSTAGE; ++t) {
        const uint32_t base = sb + (t & 1) * STAGEB;
        const bool have_next = (t + 2 < NSTAGE);
        if (have_next) ldgA(t + 2, pa);   // issue early; consumed after sync

#pragma unroll
        for (int ks = 0; ks < 4; ks++) {
            uint32_t ah[2][4], al[2][4];
#pragma unroll
            for (int i = 0; i < 2; i++) {
                const int r = rA + i * 16;
                const uint32_t addr = base + (uint32_t)(r * 128)
                                    + ((uint32_t)((ks * 2 + sseg) ^ (r & 7)) << 4);
                LDSM4(ah[i], addr);
                LDSM4(al[i], addr + 16384);
            }
            uint32_t bb[4][4];
#pragma unroll
            for (int p = 0; p < 4; p++) {
                const int r = rB0 + p * 16;
                const uint32_t addr = base + 32768 + (uint32_t)(r * 128)
                                    + ((uint32_t)((ks * 2 + sseg) ^ (r & 7)) << 4);
                LDSM4(bb[p], addr);
            }
#pragma unroll
            for (int j = 0; j < 8; j++) {
                uint32_t bf[2] = { bb[j >> 1][j & 1], bb[j >> 1][(j & 1) + 2] };
                mma_f16(acc[0][j], ah[0], bf);
                mma_f16(acc[1][j], ah[1], bf);
                mma_f16(acc[0][j], al[0], bf);
                mma_f16(acc[1][j], al[1], bf);
            }
#pragma unroll
            for (int p = 0; p < 4; p++) {
                const int r = rB0 + p * 16;
                const uint32_t addr = base + 65536 + (uint32_t)(r * 128)
                                    + ((uint32_t)((ks * 2 + sseg) ^ (r & 7)) << 4);
                LDSM4(bb[p], addr);
            }
#pragma unroll
            for (int j = 0; j < 8; j++) {
                uint32_t bf[2] = { bb[j >> 1][j & 1], bb[j >> 1][(j & 1) + 2] };
                mma_f16(acc[0][j], ah[0], bf);
                mma_f16(acc[1][j], ah[1], bf);
            }
        }
        __syncthreads();                 // everyone done reading buffer t&1
        if (have_next) {
            stsA(t + 2, pa);
            load_B(t + 2);
            asm volatile("cp.async.wait_group 1;" ::: "memory");
        } else {
            asm volatile("cp.async.wait_group 0;" ::: "memory");
        }
        __syncthreads();                 // stage t+1 fully visible
    }

    // epilogue: scale back, +b1, tanh, store f32 hidden
    const int g  = lane >> 2;
    const int tq = lane & 3;
#pragma unroll
    for (int j = 0; j < 8; j++) {
        const int col = bn + wn * 64 + j * 8 + tq * 2;
        const float bb0 = __ldg(&b1[col]);
        const float bb1 = __ldg(&b1[col + 1]);
#pragma unroll
        for (int i = 0; i < 2; i++) {
            const int row0 = bm + wm * 32 + i * 16 + g;
            float2 v0, v1;
            v0.x = tanhf(fmaf(acc[i][j][0], INV_W_SCALE, bb0));
            v0.y = tanhf(fmaf(acc[i][j][1], INV_W_SCALE, bb1));
            v1.x = tanhf(fmaf(acc[i][j][2], INV_W_SCALE, bb0));
            v1.y = tanhf(fmaf(acc[i][j][3], INV_W_SCALE, bb1));
            *(float2*)(g_hidden + (size_t)row0 * H_DIM + col)       = v0;
            *(float2*)(g_hidden + (size_t)(row0 + 8) * H_DIM + col) = v1;
        }
    }
}

// ------------------------------------------------------------- stage 2 ----
// Warp per row; no smem; W2 rows read directly (L1-resident 80KB).
__global__ __launch_bounds__(256) void stage2_kernel(
    const float* __restrict__ W2, const float* __restrict__ b2,
    const void* __restrict__ valid_mask,
    const int* __restrict__ real_actions,
    float* __restrict__ out, int B, int write_pred)
{
    __shared__ int s_mode;
    if (threadIdx.x == 0) {
        const unsigned int* m = (const unsigned int*)valid_mask;
        bool f32 = false, bf16 = false, multi = false;
#pragma unroll
        for (int i = 0; i < 64; i++) {
            unsigned int w = m[i];
            if (w == 0x3F800000u) f32 = true;
            else if (w == 0x3F803F80u || w == 0x00003F80u) bf16 = true;
            else if (w > 1u) multi = true;
        }
        s_mode = bf16 ? 3 : f32 ? 2 : multi ? 0 : 1;
    }
    __syncthreads();

    const int warp = threadIdx.x >> 5;
    const int lane = threadIdx.x & 31;
    const int row  = blockIdx.x * 8 + warp;
    if (row >= B) return;

    float acc[A_DIM];
#pragma unroll
    for (int a = 0; a < A_DIM; a++) acc[a] = 0.f;

    const float* hrow = g_hidden + (size_t)row * H_DIM;
#pragma unroll
    for (int j = 0; j < 8; j++) {
        const int k0 = j * 128 + lane * 4;
        const float4 h = __ldg((const float4*)(hrow + k0));
        const float* wb = W2 + (size_t)k0 * A_DIM;
#pragma unroll
        for (int q = 0; q < 4; q++) {
            const float hv = (&h.x)[q];
            const float* w = wb + q * A_DIM;
            const float4 w0 = __ldg((const float4*)(w + 0));
            const float4 w1 = __ldg((const float4*)(w + 4));
            const float4 w2v = __ldg((const float4*)(w + 8));
            const float4 w3 = __ldg((const float4*)(w + 12));
            const float4 w4 = __ldg((const float4*)(w + 16));
            acc[0]  = fmaf(hv, w0.x, acc[0]);   acc[1]  = fmaf(hv, w0.y, acc[1]);
            acc[2]  = fmaf(hv, w0.z, acc[2]);   acc[3]  = fmaf(hv, w0.w, acc[3]);
            acc[4]  = fmaf(hv, w1.x, acc[4]);   acc[5]  = fmaf(hv, w1.y, acc[5]);
            acc[6]  = fmaf(hv, w1.z, acc[6]);   acc[7]  = fmaf(hv, w1.w, acc[7]);
            acc[8]  = fmaf(hv, w2v.x, acc[8]);  acc[9]  = fmaf(hv, w2v.y, acc[9]);
            acc[10] = fmaf(hv, w2v.z, acc[10]); acc[11] = fmaf(hv, w2v.w, acc[11]);
            acc[12] = fmaf(hv, w3.x, acc[12]);  acc[13] = fmaf(hv, w3.y, acc[13]);
            acc[14] = fmaf(hv, w3.z, acc[14]);  acc[15] = fmaf(hv, w3.w, acc[15]);
            acc[16] = fmaf(hv, w4.x, acc[16]);  acc[17] = fmaf(hv, w4.y, acc[17]);
            acc[18] = fmaf(hv, w4.z, acc[18]);  acc[19] = fmaf(hv, w4.w, acc[19]);
        }
    }

#pragma unroll
    for (int off = 16; off > 0; off >>= 1)
#pragma unroll
        for (int a = 0; a < A_DIM; a++)
            acc[a] += __shfl_xor_sync(0xffffffffu, acc[a], off);

    if (lane == 0) {
        const int mode = s_mode;
        const long base = (long)row * A_DIM;
        float masked[A_DIM];
        float m = -3.0e38f;
#pragma unroll
        for (int a = 0; a < A_DIM; a++) {
            const float l = acc[a] + __ldg(&b2[a]);
            bool valid;
            if (mode == 1)      valid = ((const int*)valid_mask)[base + a] != 0;
            else if (mode == 2) valid = ((const float*)valid_mask)[base + a] != 0.0f;
            else if (mode == 0) valid = ((const unsigned char*)valid_mask)[base + a] != 0;
            else                valid = ((const unsigned short*)valid_mask)[base + a] != 0;
            masked[a] = valid ? l : -1e9f;
            m = fmaxf(m, masked[a]);
        }
        float s = 0.f;
#pragma unroll
        for (int a = 0; a < A_DIM; a++) s += expf(masked[a] - m);
        const float lse = m + logf(s);

        int pred = 0;
        float best = masked[0];
#pragma unroll
        for (int a = 1; a < A_DIM; a++)
            if (masked[a] > best) { best = masked[a]; pred = a; }

        const int gold = real_actions[row];
        const float loss = masked[gold] - lse;

        if (write_pred) {
            out[row]     = (float)pred;
            out[B + row] = loss;
        } else {
            out[row] = loss;
        }
    }
}

// ---------------------------------------------------------------- launch --
extern "C" void kernel_launch(void* const* d_in, const int* in_sizes, int n_in,
                              void* d_out, int out_size)
{
    const float* buffer_h = (const float*)d_in[0];
    const float* stack_h  = (const float*)d_in[1];
    const float* output_h = (const float*)d_in[2];
    const float* action_h = (const float*)d_in[3];
    const float* W1 = (const float*)d_in[4];
    const float* b1 = (const float*)d_in[5];
    const float* W2 = (const float*)d_in[6];
    const float* b2 = (const float*)d_in[7];
    const void* valid_mask = d_in[8];
    const int* real_actions = (const int*)d_in[9];
    float* out = (float*)d_out;

    const int B = in_sizes[0] / H_DIM;  // 16384

    splitB_kernel<<<dim3(H_DIM / 32, K_DIM / 32), dim3(32, 8)>>>(W1);

    const int smem1 = 2 * STAGEB;  // 192 KB
    cudaFuncSetAttribute(gemm1_fp16_kernel,
                         cudaFuncAttributeMaxDynamicSharedMemorySize, smem1);
    dim3 grid1(H_DIM / BN, B / BM);   // (4, 128)
    gemm1_fp16_kernel<<<grid1, 512, smem1>>>(buffer_h, stack_h, output_h,
                                             action_h, b1);

    const int write_pred = (out_size >= 2 * B) ? 1 : 0;
    dim3 grid2((B + 7) / 8);
    stage2_kernel<<<grid2, 256>>>(W2, b2, valid_mask, real_actions,
                                  out, B, write_pred);
}

// round 8
// speedup vs baseline: 1.0618x; 1.0482x over previous
#include <cuda_runtime.h>
#include <cuda_fp16.h>
#include <math.h>
#include <stdint.h>

#define BDIM  16384
#define H_DIM 1024
#define A_DIM 20
#define K_DIM 4096

#define BM 128
#define BN 256
#define BK 64
#define NSTAGE (K_DIM / BK)      // 64
#define STAGEB 98304             // 96 KB per stage: Ahi 16K | Alo 16K | Bhi 32K | Blo 32K
#define W_SCALE 2048.0f
#define INV_W_SCALE (1.0f / 2048.0f)

// Static scratch (no allocations allowed)
__device__ __align__(1024) float  g_hidden[(size_t)BDIM * H_DIM];  // 64 MB
__device__ __align__(1024) __half g_Ahi[(size_t)BDIM * K_DIM];     // 128 MB
__device__ __align__(1024) __half g_Alo[(size_t)BDIM * K_DIM];     // 128 MB
__device__ __align__(1024) __half g_Bhi[(size_t)H_DIM * K_DIM];    // 8 MB (2048*W1^T hi)
__device__ __align__(1024) __half g_Blo[(size_t)H_DIM * K_DIM];    // 8 MB

// ---------------------------------------------------------------- helpers --
__device__ __forceinline__ uint32_t smem_u32(const void* p) {
    uint32_t a;
    asm("{ .reg .u64 t; cvta.to.shared.u64 t, %1; cvt.u32.u64 %0, t; }"
        : "=r"(a) : "l"(p));
    return a;
}
__device__ __forceinline__ void cp_async16(uint32_t dst, const void* src) {
    asm volatile("cp.async.cg.shared.global [%0], [%1], 16;" :: "r"(dst), "l"(src));
}
#define SW128(o) ((o) ^ (((o) >> 3) & 0x70))

#define LDSM4(r, addr) \
    asm volatile("ldmatrix.sync.aligned.m8n8.x4.shared.b16 {%0,%1,%2,%3}, [%4];" \
        : "=r"((r)[0]), "=r"((r)[1]), "=r"((r)[2]), "=r"((r)[3]) : "r"(addr))

__device__ __forceinline__ void mma_f16(float* c, const uint32_t* a, const uint32_t* b) {
    asm volatile(
        "mma.sync.aligned.m16n8k16.row.col.f32.f16.f16.f32 "
        "{%0,%1,%2,%3},{%4,%5,%6,%7},{%8,%9},{%0,%1,%2,%3};"
        : "+f"(c[0]), "+f"(c[1]), "+f"(c[2]), "+f"(c[3])
        : "r"(a[0]), "r"(a[1]), "r"(a[2]), "r"(a[3]), "r"(b[0]), "r"(b[1]));
}

// ------------------------------------------------------------- pre-passes --
__global__ __launch_bounds__(256) void splitA_kernel(
    const float* __restrict__ x0, const float* __restrict__ x1,
    const float* __restrict__ x2, const float* __restrict__ x3)
{
    const size_t i = (size_t)blockIdx.x * blockDim.x + threadIdx.x;  // float4 idx
    if (i >= (size_t)BDIM * K_DIM / 4) return;
    const size_t m = i >> 10;
    const int kq = (int)(i & 1023);
    const int part = kq >> 8;
    const int kin = (kq & 255) * 4;
    const float* xs = part == 0 ? x0 : part == 1 ? x1 : part == 2 ? x2 : x3;
    float4 a = *(const float4*)(xs + m * H_DIM + kin);

    __half h0 = __float2half_rn(a.x), h1 = __float2half_rn(a.y);
    __half h2 = __float2half_rn(a.z), h3 = __float2half_rn(a.w);
    __half l0 = __float2half_rn(a.x - __half2float(h0));
    __half l1 = __float2half_rn(a.y - __half2float(h1));
    __half l2 = __float2half_rn(a.z - __half2float(h2));
    __half l3 = __float2half_rn(a.w - __half2float(h3));

    __half2* ph = (__half2*)(g_Ahi + i * 4);
    __half2* pl = (__half2*)(g_Alo + i * 4);
    ph[0] = __halves2half2(h0, h1); ph[1] = __halves2half2(h2, h3);
    pl[0] = __halves2half2(l0, l1); pl[1] = __halves2half2(l2, l3);
}

__global__ void splitB_kernel(const float* __restrict__ W1)
{
    __shared__ float tile[32][33];
    const int k0 = blockIdx.y * 32;
    const int n0 = blockIdx.x * 32;
    const int tx = threadIdx.x, ty = threadIdx.y;
#pragma unroll
    for (int j = 0; j < 32; j += 8)
        tile[ty + j][tx] = W1[(size_t)(k0 + ty + j) * H_DIM + n0 + tx];
    __syncthreads();
#pragma unroll
    for (int j = 0; j < 32; j += 8) {
        const int n = n0 + ty + j, k = k0 + tx;
        const float v = tile[tx][ty + j] * W_SCALE;
        const __half h = __float2half_rn(v);
        g_Bhi[(size_t)n * K_DIM + k] = h;
        g_Blo[(size_t)n * K_DIM + k] = __float2half_rn(v - __half2float(h));
    }
}

// ------------------------------------------- stage 1: fp16x3 mma GEMM ------
__global__ __launch_bounds__(512, 1) void gemm1_fp16_kernel(const float* __restrict__ b1)
{
    extern __shared__ char smem[];
    const uint32_t sb = smem_u32(smem);
    const int tid  = threadIdx.x;
    const int wid  = tid >> 5;
    const int lane = tid & 31;
    const int wm = wid & 3;     // 4 m-tiles of 32
    const int wn = wid >> 2;    // 4 n-tiles of 64
    const int bm = blockIdx.y * BM;
    const int bn = blockIdx.x * BN;

    auto load_stage = [&](int t) {
        const int st = t & 1;
        const int k0 = t * BK;
        const uint32_t base = sb + st * STAGEB;
#pragma unroll
        for (int c = 0; c < 4; c++) {                 // A: 2048 chunks
            const int idx = c * 512 + tid;
            const int plane = idx >> 10, rem = idx & 1023;
            const int r = rem >> 3, seg = rem & 7;
            const __half* gp = plane ? g_Alo : g_Ahi;
            cp_async16(base + plane * 16384 + SW128((uint32_t)(r * 128 + seg * 16)),
                       gp + (size_t)(bm + r) * K_DIM + k0 + seg * 8);
        }
#pragma unroll
        for (int c = 0; c < 8; c++) {                 // B: 4096 chunks
            const int idx = c * 512 + tid;
            const int plane = idx >> 11, rem = idx & 2047;
            const int r = rem >> 3, seg = rem & 7;
            const __half* gp = plane ? g_Blo : g_Bhi;
            cp_async16(base + 32768 + plane * 32768 + SW128((uint32_t)(r * 128 + seg * 16)),
                       gp + (size_t)(bn + r) * K_DIM + k0 + seg * 8);
        }
        asm volatile("cp.async.commit_group;" ::: "memory");
    };

    float acc[2][8][4];
#pragma unroll
    for (int i = 0; i < 2; i++)
#pragma unroll
        for (int j = 0; j < 8; j++)
#pragma unroll
            for (int q = 0; q < 4; q++) acc[i][j][q] = 0.f;

    load_stage(0);
    load_stage(1);
    asm volatile("cp.async.wait_group 1;" ::: "memory");
    __syncthreads();

    const int rA = wm * 32 + (lane & 15);
    const int rB0 = wn * 64 + (lane & 15);
    const int sseg = lane >> 4;

    for (int t = 0; t < NSTAGE; ++t) {
        const uint32_t base = sb + (t & 1) * STAGEB;
#pragma unroll
        for (int ks = 0; ks < 4; ks++) {
            uint32_t ah[2][4], al[2][4];
#pragma unroll
            for (int i = 0; i < 2; i++) {
                const int r = rA + i * 16;
                const uint32_t addr = base + (uint32_t)(r * 128)
                                    + ((uint32_t)((ks * 2 + sseg) ^ (r & 7)) << 4);
                LDSM4(ah[i], addr);
                LDSM4(al[i], addr + 16384);
            }
            uint32_t bb[4][4];
#pragma unroll
            for (int p = 0; p < 4; p++) {
                const int r = rB0 + p * 16;
                const uint32_t addr = base + 32768 + (uint32_t)(r * 128)
                                    + ((uint32_t)((ks * 2 + sseg) ^ (r & 7)) << 4);
                LDSM4(bb[p], addr);
            }
#pragma unroll
            for (int j = 0; j < 8; j++) {
                uint32_t bf[2] = { bb[j >> 1][j & 1], bb[j >> 1][(j & 1) + 2] };
                mma_f16(acc[0][j], ah[0], bf);
                mma_f16(acc[1][j], ah[1], bf);
                mma_f16(acc[0][j], al[0], bf);
                mma_f16(acc[1][j], al[1], bf);
            }
#pragma unroll
            for (int p = 0; p < 4; p++) {
                const int r = rB0 + p * 16;
                const uint32_t addr = base + 65536 + (uint32_t)(r * 128)
                                    + ((uint32_t)((ks * 2 + sseg) ^ (r & 7)) << 4);
                LDSM4(bb[p], addr);
            }
#pragma unroll
            for (int j = 0; j < 8; j++) {
                uint32_t bf[2] = { bb[j >> 1][j & 1], bb[j >> 1][(j & 1) + 2] };
                mma_f16(acc[0][j], ah[0], bf);
                mma_f16(acc[1][j], ah[1], bf);
            }
        }
        __syncthreads();
        if (t + 2 < NSTAGE) {
            load_stage(t + 2);
            asm volatile("cp.async.wait_group 1;" ::: "memory");
        } else {
            asm volatile("cp.async.wait_group 0;" ::: "memory");
        }
        __syncthreads();
    }

    // epilogue: scale back, +b1, tanh
    const int g  = lane >> 2;
    const int tq = lane & 3;
#pragma unroll
    for (int j = 0; j < 8; j++) {
        const int col = bn + wn * 64 + j * 8 + tq * 2;
        const float bb0 = __ldg(&b1[col]);
        const float bb1 = __ldg(&b1[col + 1]);
#pragma unroll
        for (int i = 0; i < 2; i++) {
            const int row0 = bm + wm * 32 + i * 16 + g;
            float2 v0, v1;
            v0.x = tanhf(fmaf(acc[i][j][0], INV_W_SCALE, bb0));
            v0.y = tanhf(fmaf(acc[i][j][1], INV_W_SCALE, bb1));
            v1.x = tanhf(fmaf(acc[i][j][2], INV_W_SCALE, bb0));
            v1.y = tanhf(fmaf(acc[i][j][3], INV_W_SCALE, bb1));
            *(float2*)(g_hidden + (size_t)row0 * H_DIM + col)       = v0;
            *(float2*)(g_hidden + (size_t)(row0 + 8) * H_DIM + col) = v1;
        }
    }
}

// ------------------------------------------------------------- stage 2 ----
// v3: 512 threads (16 warps), 80KB smem W2^T, 2 rows per warp, float4 LDS.
__global__ __launch_bounds__(512) void stage2_kernel(
    const float* __restrict__ W2, const float* __restrict__ b2,
    const void* __restrict__ valid_mask,
    const int* __restrict__ real_actions,
    float* __restrict__ out, int B, int write_pred)
{
    extern __shared__ float W2t[];  // [20][1024]
    __shared__ int s_mode;
    if (threadIdx.x == 0) {
        const unsigned int* m = (const unsigned int*)valid_mask;
        bool f32 = false, bf16 = false, multi = false;
#pragma unroll
        for (int i = 0; i < 64; i++) {
            unsigned int w = m[i];
            if (w == 0x3F800000u) f32 = true;
            else if (w == 0x3F803F80u || w == 0x00003F80u) bf16 = true;
            else if (w > 1u) multi = true;
        }
        s_mode = bf16 ? 3 : f32 ? 2 : multi ? 0 : 1;
    }
    for (int i = threadIdx.x; i < A_DIM * H_DIM; i += blockDim.x) {
        const int a = i >> 10;
        const int k = i & 1023;
        W2t[a * H_DIM + k] = W2[k * A_DIM + a];
    }
    __syncthreads();

    const int warp = threadIdx.x >> 5;
    const int lane = threadIdx.x & 31;
    const int row0 = blockIdx.x * 32 + warp * 2;    // 2 rows per warp
    if (row0 >= B) return;

    float acc0[A_DIM], acc1[A_DIM];
#pragma unroll
    for (int a = 0; a < A_DIM; a++) { acc0[a] = 0.f; acc1[a] = 0.f; }

    const float* h0 = g_hidden + (size_t)row0 * H_DIM;
    const float* h1 = h0 + H_DIM;
#pragma unroll
    for (int j = 0; j < 8; j++) {
        const int k = j * 128 + lane * 4;
        const float4 v0 = *(const float4*)(h0 + k);
        const float4 v1 = *(const float4*)(h1 + k);
#pragma unroll
        for (int a = 0; a < A_DIM; a++) {
            const float4 w = *(const float4*)(W2t + a * H_DIM + k);
            acc0[a] = fmaf(v0.x, w.x, fmaf(v0.y, w.y, fmaf(v0.z, w.z, fmaf(v0.w, w.w, acc0[a]))));
            acc1[a] = fmaf(v1.x, w.x, fmaf(v1.y, w.y, fmaf(v1.z, w.z, fmaf(v1.w, w.w, acc1[a]))));
        }
    }

#pragma unroll
    for (int off = 16; off > 0; off >>= 1)
#pragma unroll
        for (int a = 0; a < A_DIM; a++) {
            acc0[a] += __shfl_xor_sync(0xffffffffu, acc0[a], off);
            acc1[a] += __shfl_xor_sync(0xffffffffu, acc1[a], off);
        }

    if (lane < 2) {
        const float* accp = lane == 0 ? acc0 : acc1;
        const int row = row0 + lane;
        const int mode = s_mode;
        const long base = (long)row * A_DIM;
        float masked[A_DIM];
        float m = -3.0e38f;
#pragma unroll
        for (int a = 0; a < A_DIM; a++) {
            const float l = accp[a] + __ldg(&b2[a]);
            bool valid;
            if (mode == 1)      valid = ((const int*)valid_mask)[base + a] != 0;
            else if (mode == 2) valid = ((const float*)valid_mask)[base + a] != 0.0f;
            else if (mode == 0) valid = ((const unsigned char*)valid_mask)[base + a] != 0;
            else                valid = ((const unsigned short*)valid_mask)[base + a] != 0;
            masked[a] = valid ? l : -1e9f;
            m = fmaxf(m, masked[a]);
        }
        float s = 0.f;
#pragma unroll
        for (int a = 0; a < A_DIM; a++) s += expf(masked[a] - m);
        const float lse = m + logf(s);

        int pred = 0;
        float best = masked[0];
#pragma unroll
        for (int a = 1; a < A_DIM; a++)
            if (masked[a] > best) { best = masked[a]; pred = a; }

        const int gold = real_actions[row];
        const float loss = masked[gold] - lse;

        if (write_pred) {
            out[row]     = (float)pred;
            out[B + row] = loss;
        } else {
            out[row] = loss;
        }
    }
}

// ---------------------------------------------------------------- launch --
extern "C" void kernel_launch(void* const* d_in, const int* in_sizes, int n_in,
                              void* d_out, int out_size)
{
    const float* buffer_h = (const float*)d_in[0];
    const float* stack_h  = (const float*)d_in[1];
    const float* output_h = (const float*)d_in[2];
    const float* action_h = (const float*)d_in[3];
    const float* W1 = (const float*)d_in[4];
    const float* b1 = (const float*)d_in[5];
    const float* W2 = (const float*)d_in[6];
    const float* b2 = (const float*)d_in[7];
    const void* valid_mask = d_in[8];
    const int* real_actions = (const int*)d_in[9];
    float* out = (float*)d_out;

    const int B = in_sizes[0] / H_DIM;  // 16384

    const size_t totalA4 = (size_t)B * K_DIM / 4;
    splitA_kernel<<<(unsigned)((totalA4 + 255) / 256), 256>>>(buffer_h, stack_h,
                                                              output_h, action_h);
    splitB_kernel<<<dim3(H_DIM / 32, K_DIM / 32), dim3(32, 8)>>>(W1);

    const int smem1 = 2 * STAGEB;  // 192 KB
    cudaFuncSetAttribute(gemm1_fp16_kernel,
                         cudaFuncAttributeMaxDynamicSharedMemorySize, smem1);
    dim3 grid1(H_DIM / BN, B / BM);   // (4, 128)
    gemm1_fp16_kernel<<<grid1, 512, smem1>>>(b1);

    static const size_t smem2 = (size_t)A_DIM * H_DIM * sizeof(float);
    cudaFuncSetAttribute(stage2_kernel,
                         cudaFuncAttributeMaxDynamicSharedMemorySize, (int)smem2);
    const int write_pred = (out_size >= 2 * B) ? 1 : 0;
    dim3 grid2(B / 32);
    stage2_kernel<<<grid2, 512, smem2>>>(W2, b2, valid_mask, real_actions,
                                         out, B, write_pred);
}

// round 9
// speedup vs baseline: 1.1300x; 1.0642x over previous
#include <cuda_runtime.h>
#include <cuda_fp16.h>
#include <math.h>
#include <stdint.h>

#define BDIM  16384
#define H_DIM 1024
#define A_DIM 20
#define K_DIM 4096

#define BM 128
#define BN 128
#define BK 32
#define NSTAGE (K_DIM / BK)      // 128
#define STAGEB 32768             // 32 KB: Ahi 8K | Alo 8K | Bhi 8K | Blo 8K
#define W_SCALE 2048.0f
#define INV_W_SCALE (1.0f / 2048.0f)

// Static scratch (no allocations allowed)
__device__ __align__(1024) float  g_hidden[(size_t)BDIM * H_DIM];  // 64 MB
__device__ __align__(1024) __half g_Ahi[(size_t)BDIM * K_DIM];     // 128 MB
__device__ __align__(1024) __half g_Alo[(size_t)BDIM * K_DIM];     // 128 MB
__device__ __align__(1024) __half g_Bhi[(size_t)H_DIM * K_DIM];    // 8 MB (2048*W1^T hi)
__device__ __align__(1024) __half g_Blo[(size_t)H_DIM * K_DIM];    // 8 MB

// ---------------------------------------------------------------- helpers --
__device__ __forceinline__ uint32_t smem_u32(const void* p) {
    uint32_t a;
    asm("{ .reg .u64 t; cvta.to.shared.u64 t, %1; cvt.u32.u64 %0, t; }"
        : "=r"(a) : "l"(p));
    return a;
}
__device__ __forceinline__ void cp_async16(uint32_t dst, const void* src) {
    asm volatile("cp.async.cg.shared.global [%0], [%1], 16;" :: "r"(dst), "l"(src));
}

#define LDSM4(r, addr) \
    asm volatile("ldmatrix.sync.aligned.m8n8.x4.shared.b16 {%0,%1,%2,%3}, [%4];" \
        : "=r"((r)[0]), "=r"((r)[1]), "=r"((r)[2]), "=r"((r)[3]) : "r"(addr))

__device__ __forceinline__ void mma_f16(float* c, const uint32_t* a, const uint32_t* b) {
    asm volatile(
        "mma.sync.aligned.m16n8k16.row.col.f32.f16.f16.f32 "
        "{%0,%1,%2,%3},{%4,%5,%6,%7},{%8,%9},{%0,%1,%2,%3};"
        : "+f"(c[0]), "+f"(c[1]), "+f"(c[2]), "+f"(c[3])
        : "r"(a[0]), "r"(a[1]), "r"(a[2]), "r"(a[3]), "r"(b[0]), "r"(b[1]));
}

// Two logical 32-half rows packed per 128B smem row, SW128 within the row.
// logical row r, 16B seg s (0..3) -> phys offset
__device__ __forceinline__ uint32_t tile_off(int r, int s) {
    const uint32_t cc = ((uint32_t)(r & 1) << 2) + (uint32_t)s;
    return (uint32_t)(r >> 1) * 128u + ((cc ^ ((uint32_t)(r >> 1) & 7u)) << 4);
}

// ------------------------------------------------------------- pre-passes --
__global__ __launch_bounds__(256) void splitA_kernel(
    const float* __restrict__ x0, const float* __restrict__ x1,
    const float* __restrict__ x2, const float* __restrict__ x3)
{
    const size_t i = (size_t)blockIdx.x * blockDim.x + threadIdx.x;  // float4 idx
    if (i >= (size_t)BDIM * K_DIM / 4) return;
    const size_t m = i >> 10;
    const int kq = (int)(i & 1023);
    const int part = kq >> 8;
    const int kin = (kq & 255) * 4;
    const float* xs = part == 0 ? x0 : part == 1 ? x1 : part == 2 ? x2 : x3;
    float4 a = *(const float4*)(xs + m * H_DIM + kin);

    __half h0 = __float2half_rn(a.x), h1 = __float2half_rn(a.y);
    __half h2 = __float2half_rn(a.z), h3 = __float2half_rn(a.w);
    __half l0 = __float2half_rn(a.x - __half2float(h0));
    __half l1 = __float2half_rn(a.y - __half2float(h1));
    __half l2 = __float2half_rn(a.z - __half2float(h2));
    __half l3 = __float2half_rn(a.w - __half2float(h3));

    __half2* ph = (__half2*)(g_Ahi + i * 4);
    __half2* pl = (__half2*)(g_Alo + i * 4);
    ph[0] = __halves2half2(h0, h1); ph[1] = __halves2half2(h2, h3);
    pl[0] = __halves2half2(l0, l1); pl[1] = __halves2half2(l2, l3);
}

__global__ void splitB_kernel(const float* __restrict__ W1)
{
    __shared__ float tile[32][33];
    const int k0 = blockIdx.y * 32;
    const int n0 = blockIdx.x * 32;
    const int tx = threadIdx.x, ty = threadIdx.y;
#pragma unroll
    for (int j = 0; j < 32; j += 8)
        tile[ty + j][tx] = W1[(size_t)(k0 + ty + j) * H_DIM + n0 + tx];
    __syncthreads();
#pragma unroll
    for (int j = 0; j < 32; j += 8) {
        const int n = n0 + ty + j, k = k0 + tx;
        const float v = tile[tx][ty + j] * W_SCALE;
        const __half h = __float2half_rn(v);
        g_Bhi[(size_t)n * K_DIM + k] = h;
        g_Blo[(size_t)n * K_DIM + k] = __float2half_rn(v - __half2float(h));
    }
}

// ------------------------------------------- stage 1: fp16x3 mma GEMM ------
// 128x128x32 tiles, 256 threads, 2 CTAs/SM.
__global__ __launch_bounds__(256, 2) void gemm1_fp16_kernel(const float* __restrict__ b1)
{
    extern __shared__ char smem[];
    const uint32_t sb = smem_u32(smem);
    const int tid  = threadIdx.x;
    const int wid  = tid >> 5;
    const int lane = tid & 31;
    const int wm = wid & 3;     // 4 m-tiles of 32
    const int wn = wid >> 2;    // 2 n-tiles of 64
    const int bm = blockIdx.y * BM;
    const int bn = blockIdx.x * BN;

    // loader: A 1024 chunks (2 planes x 128 rows x 4 segs), B same; 4+4/thread
    auto load_stage = [&](int t) {
        const uint32_t base = sb + (t & 1) * STAGEB;
        const int k0 = t * BK;
#pragma unroll
        for (int c = 0; c < 4; c++) {
            const int idx = c * 256 + tid;
            const int plane = idx >> 9, rem = idx & 511;
            const int r = rem >> 2, seg = rem & 3;
            const __half* gp = plane ? g_Alo : g_Ahi;
            cp_async16(base + plane * 8192 + tile_off(r, seg),
                       gp + (size_t)(bm + r) * K_DIM + k0 + seg * 8);
        }
#pragma unroll
        for (int c = 0; c < 4; c++) {
            const int idx = c * 256 + tid;
            const int plane = idx >> 9, rem = idx & 511;
            const int r = rem >> 2, seg = rem & 3;
            const __half* gp = plane ? g_Blo : g_Bhi;
            cp_async16(base + 16384 + plane * 8192 + tile_off(r, seg),
                       gp + (size_t)(bn + r) * K_DIM + k0 + seg * 8);
        }
        asm volatile("cp.async.commit_group;" ::: "memory");
    };

    float acc[2][8][4];
#pragma unroll
    for (int i = 0; i < 2; i++)
#pragma unroll
        for (int j = 0; j < 8; j++)
#pragma unroll
            for (int q = 0; q < 4; q++) acc[i][j][q] = 0.f;

    load_stage(0);
    load_stage(1);
    asm volatile("cp.async.wait_group 1;" ::: "memory");
    __syncthreads();

    const int rA  = wm * 32 + (lane & 15);
    const int rB0 = wn * 64 + (lane & 15);
    const int sseg = lane >> 4;

    for (int t = 0; t < NSTAGE; ++t) {
        const uint32_t base = sb + (t & 1) * STAGEB;
#pragma unroll
        for (int ks = 0; ks < 2; ks++) {
            const int kseg = ks * 2 + sseg;          // 0..3
            uint32_t ah[2][4], al[2][4];
#pragma unroll
            for (int i = 0; i < 2; i++) {
                const int r = rA + i * 16;
                const uint32_t addr = base + tile_off(r, kseg);
                LDSM4(ah[i], addr);
                LDSM4(al[i], addr + 8192);
            }
            uint32_t bb[4][4];
#pragma unroll
            for (int p = 0; p < 4; p++) {
                const int r = rB0 + p * 16;
                LDSM4(bb[p], base + 16384 + tile_off(r, kseg));
            }
#pragma unroll
            for (int j = 0; j < 8; j++) {
                uint32_t bf[2] = { bb[j >> 1][j & 1], bb[j >> 1][(j & 1) + 2] };
                mma_f16(acc[0][j], ah[0], bf);
                mma_f16(acc[1][j], ah[1], bf);
                mma_f16(acc[0][j], al[0], bf);
                mma_f16(acc[1][j], al[1], bf);
            }
#pragma unroll
            for (int p = 0; p < 4; p++) {
                const int r = rB0 + p * 16;
                LDSM4(bb[p], base + 24576 + tile_off(r, kseg));
            }
#pragma unroll
            for (int j = 0; j < 8; j++) {
                uint32_t bf[2] = { bb[j >> 1][j & 1], bb[j >> 1][(j & 1) + 2] };
                mma_f16(acc[0][j], ah[0], bf);
                mma_f16(acc[1][j], ah[1], bf);
            }
        }
        __syncthreads();
        if (t + 2 < NSTAGE) {
            load_stage(t + 2);
            asm volatile("cp.async.wait_group 1;" ::: "memory");
        } else {
            asm volatile("cp.async.wait_group 0;" ::: "memory");
        }
        __syncthreads();
    }

    // epilogue: scale back, +b1, tanh
    const int g  = lane >> 2;
    const int tq = lane & 3;
#pragma unroll
    for (int j = 0; j < 8; j++) {
        const int col = bn + wn * 64 + j * 8 + tq * 2;
        const float bb0 = __ldg(&b1[col]);
        const float bb1 = __ldg(&b1[col + 1]);
#pragma unroll
        for (int i = 0; i < 2; i++) {
            const int row0 = bm + wm * 32 + i * 16 + g;
            float2 v0, v1;
            v0.x = tanhf(fmaf(acc[i][j][0], INV_W_SCALE, bb0));
            v0.y = tanhf(fmaf(acc[i][j][1], INV_W_SCALE, bb1));
            v1.x = tanhf(fmaf(acc[i][j][2], INV_W_SCALE, bb0));
            v1.y = tanhf(fmaf(acc[i][j][3], INV_W_SCALE, bb1));
            *(float2*)(g_hidden + (size_t)row0 * H_DIM + col)       = v0;
            *(float2*)(g_hidden + (size_t)(row0 + 8) * H_DIM + col) = v1;
        }
    }
}

// ------------------------------------------------------------- stage 2 ----
// 512 threads (16 warps), 80KB smem W2^T, 2 rows per warp, float4 LDS.
__global__ __launch_bounds__(512) void stage2_kernel(
    const float* __restrict__ W2, const float* __restrict__ b2,
    const void* __restrict__ valid_mask,
    const int* __restrict__ real_actions,
    float* __restrict__ out, int B, int write_pred)
{
    extern __shared__ float W2t[];  // [20][1024]
    __shared__ int s_mode;
    if (threadIdx.x == 0) {
        const unsigned int* m = (const unsigned int*)valid_mask;
        bool f32 = false, bf16 = false, multi = false;
#pragma unroll
        for (int i = 0; i < 64; i++) {
            unsigned int w = m[i];
            if (w == 0x3F800000u) f32 = true;
            else if (w == 0x3F803F80u || w == 0x00003F80u) bf16 = true;
            else if (w > 1u) multi = true;
        }
        s_mode = bf16 ? 3 : f32 ? 2 : multi ? 0 : 1;
    }
    for (int i = threadIdx.x; i < A_DIM * H_DIM; i += blockDim.x) {
        const int a = i >> 10;
        const int k = i & 1023;
        W2t[a * H_DIM + k] = W2[k * A_DIM + a];
    }
    __syncthreads();

    const int warp = threadIdx.x >> 5;
    const int lane = threadIdx.x & 31;
    const int row0 = blockIdx.x * 32 + warp * 2;
    if (row0 >= B) return;

    float acc0[A_DIM], acc1[A_DIM];
#pragma unroll
    for (int a = 0; a < A_DIM; a++) { acc0[a] = 0.f; acc1[a] = 0.f; }

    const float* h0 = g_hidden + (size_t)row0 * H_DIM;
    const float* h1 = h0 + H_DIM;
#pragma unroll
    for (int j = 0; j < 8; j++) {
        const int k = j * 128 + lane * 4;
        const float4 v0 = *(const float4*)(h0 + k);
        const float4 v1 = *(const float4*)(h1 + k);
#pragma unroll
        for (int a = 0; a < A_DIM; a++) {
            const float4 w = *(const float4*)(W2t + a * H_DIM + k);
            acc0[a] = fmaf(v0.x, w.x, fmaf(v0.y, w.y, fmaf(v0.z, w.z, fmaf(v0.w, w.w, acc0[a]))));
            acc1[a] = fmaf(v1.x, w.x, fmaf(v1.y, w.y, fmaf(v1.z, w.z, fmaf(v1.w, w.w, acc1[a]))));
        }
    }

#pragma unroll
    for (int off = 16; off > 0; off >>= 1)
#pragma unroll
        for (int a = 0; a < A_DIM; a++) {
            acc0[a] += __shfl_xor_sync(0xffffffffu, acc0[a], off);
            acc1[a] += __shfl_xor_sync(0xffffffffu, acc1[a], off);
        }

    if (lane < 2) {
        const float* accp = lane == 0 ? acc0 : acc1;
        const int row = row0 + lane;
        const int mode = s_mode;
        const long base = (long)row * A_DIM;
        float masked[A_DIM];
        float m = -3.0e38f;
#pragma unroll
        for (int a = 0; a < A_DIM; a++) {
            const float l = accp[a] + __ldg(&b2[a]);
            bool valid;
            if (mode == 1)      valid = ((const int*)valid_mask)[base + a] != 0;
            else if (mode == 2) valid = ((const float*)valid_mask)[base + a] != 0.0f;
            else if (mode == 0) valid = ((const unsigned char*)valid_mask)[base + a] != 0;
            else                valid = ((const unsigned short*)valid_mask)[base + a] != 0;
            masked[a] = valid ? l : -1e9f;
            m = fmaxf(m, masked[a]);
        }
        float s = 0.f;
#pragma unroll
        for (int a = 0; a < A_DIM; a++) s += expf(masked[a] - m);
        const float lse = m + logf(s);

        int pred = 0;
        float best = masked[0];
#pragma unroll
        for (int a = 1; a < A_DIM; a++)
            if (masked[a] > best) { best = masked[a]; pred = a; }

        const int gold = real_actions[row];
        const float loss = masked[gold] - lse;

        if (write_pred) {
            out[row]     = (float)pred;
            out[B + row] = loss;
        } else {
            out[row] = loss;
        }
    }
}

// ---------------------------------------------------------------- launch --
extern "C" void kernel_launch(void* const* d_in, const int* in_sizes, int n_in,
                              void* d_out, int out_size)
{
    const float* buffer_h = (const float*)d_in[0];
    const float* stack_h  = (const float*)d_in[1];
    const float* output_h = (const float*)d_in[2];
    const float* action_h = (const float*)d_in[3];
    const float* W1 = (const float*)d_in[4];
    const float* b1 = (const float*)d_in[5];
    const float* W2 = (const float*)d_in[6];
    const float* b2 = (const float*)d_in[7];
    const void* valid_mask = d_in[8];
    const int* real_actions = (const int*)d_in[9];
    float* out = (float*)d_out;

    const int B = in_sizes[0] / H_DIM;  // 16384

    const size_t totalA4 = (size_t)B * K_DIM / 4;
    splitA_kernel<<<(unsigned)((totalA4 + 255) / 256), 256>>>(buffer_h, stack_h,
                                                              output_h, action_h);
    splitB_kernel<<<dim3(H_DIM / 32, K_DIM / 32), dim3(32, 8)>>>(W1);

    const int smem1 = 2 * STAGEB;  // 64 KB
    cudaFuncSetAttribute(gemm1_fp16_kernel,
                         cudaFuncAttributeMaxDynamicSharedMemorySize, smem1);
    dim3 grid1(H_DIM / BN, B / BM);   // (8, 128) = 1024 tiles
    gemm1_fp16_kernel<<<grid1, 256, smem1>>>(b1);

    static const size_t smem2 = (size_t)A_DIM * H_DIM * sizeof(float);
    cudaFuncSetAttribute(stage2_kernel,
                         cudaFuncAttributeMaxDynamicSharedMemorySize, (int)smem2);
    const int write_pred = (out_size >= 2 * B) ? 1 : 0;
    dim3 grid2(B / 32);
    stage2_kernel<<<grid2, 512, smem2>>>(W2, b2, valid_mask, real_actions,
                                         out, B, write_pred);
}